// round 4
// baseline (speedup 1.0000x reference)
#include <cuda_runtime.h>

#define DD 256      // feature/hidden dim
#define GD 768      // 3*DD gate dim
#define LL 96       // max group length
#define TG 14       // groups per block
#define TGH 7       // groups per warpgroup-half
#define BMAX 2048
#define NT 1024     // 4 warpgroups: (ih,hh) x (lo,hi)

typedef unsigned long long u64;

// ---------------- device scratch ----------------
__device__ int    g_order[BMAX * LL];          // edge id per (group, t), -1 = pad
__device__ float4 g_wpack[4 * 64 * GD];        // [mat][kb][gd] -> W[gd][4kb..4kb+3]

// ---------------- helpers ----------------
__device__ __forceinline__ u64 fma2(u64 a, u64 b, u64 c) {
    u64 d;
    asm("fma.rn.f32x2 %0, %1, %2, %3;" : "=l"(d) : "l"(a), "l"(b), "l"(c));
    return d;
}
__device__ __forceinline__ float red2(u64 a) {
    float lo = __uint_as_float((unsigned)(a & 0xffffffffULL));
    float hi = __uint_as_float((unsigned)(a >> 32));
    return lo + hi;
}
__device__ __forceinline__ u64 set_lo(float v) { return (u64)__float_as_uint(v); }

__device__ __forceinline__ float sigmoidf_(float v) {
    return __fdividef(1.f, 1.f + __expf(-v));
}
__device__ __forceinline__ float tanhf_(float v) {
    float t = __expf(2.f * v);
    return 1.f - __fdividef(2.f, t + 1.f);
}

// ---------------- fused setup: per-group timestamp sort + weight pack ----------------
__global__ void setup_k(const float* __restrict__ ts, const int* __restrict__ index,
                        int E, int B,
                        const float* __restrict__ w0, const float* __restrict__ w1,
                        const float* __restrict__ w2, const float* __restrict__ w3)
{
    const int b = blockIdx.x;
    if (b < B) {
        __shared__ int   lbub[2];
        __shared__ float sts[LL];
        const int i = threadIdx.x;
        if (i < 2) {
            const int key = b + i;
            int lo = 0, hi = E;
            while (lo < hi) {
                int m = (lo + hi) >> 1;
                if (index[m] < key) lo = m + 1; else hi = m;
            }
            lbub[i] = lo;
        }
        __syncthreads();
        const int off = lbub[0];
        const int c   = lbub[1] - lbub[0];
        if (i < c)  sts[i] = ts[off + i];
        if (i < LL) g_order[b * LL + i] = -1;
        __syncthreads();
        if (i < c) {
            const float ti = sts[i];
            int rank = 0;
            for (int j = 0; j < c; ++j) {
                float tj = sts[j];
                rank += (tj < ti || (tj == ti && j < i)) ? 1 : 0;
            }
            g_order[b * LL + (LL - c + rank)] = off + i;
        }
    } else {
        int idx = (b - B) * 256 + threadIdx.x;
        if (idx < 4 * 64 * GD) {
            int m   = idx / (64 * GD);
            int rem = idx - m * 64 * GD;
            int kb  = rem / GD;
            int dd  = rem - kb * GD;
            const float* W = (m == 0) ? w0 : (m == 1) ? w1 : (m == 2) ? w2 : w3;
            const float* p = W + dd * DD + kb * 4;
            g_wpack[idx] = make_float4(p[0], p[1], p[2], p[3]);
        }
    }
}

// ---------------- one layer, one timestep (all 4 warpgroups) ----------------
// ih warpgroups (side=0): stream W_ih against `opsrc` (layer input) for their 7
//   groups, then combine with hh partials from smem, apply activations, update
//   hstate (and pooled accs for layer 1).
// hh warpgroups (side=1): stream W_hh against hstate (old h), publish partials.
__device__ __forceinline__ void layer_pass(
    const float4* __restrict__ wmat,
    const float* __restrict__ bvec,
    const float* __restrict__ opsrc,           // [TG][DD]
    float* __restrict__ hstate,                // [TG][DD]
    float* __restrict__ ph,                    // [TG][3][DD]
    float* __restrict__ accs,                  // [TG][DD] or nullptr
    int side, int gb, int d)
{
    u64 a0[TGH], a1[TGH], a2[TGH];
    {
        const u64 br = set_lo(bvec[d]);
        const u64 bz = set_lo(bvec[DD + d]);
        const u64 bn = set_lo(bvec[2 * DD + d]);
#pragma unroll
        for (int g = 0; g < TGH; ++g) { a0[g] = br; a1[g] = bz; a2[g] = bn; }
    }

    const char* wp = (const char*)(wmat + d);          // +GD*16 bytes per kb
    const char* op = (const char*)(opsrc + gb * DD);   // +16 bytes per kb

#pragma unroll 1
    for (int kb = 0; kb < 64; ++kb) {
        ulonglong2 wr = *(const ulonglong2*)(wp);
        ulonglong2 wz = *(const ulonglong2*)(wp + DD * 16);
        ulonglong2 wn = *(const ulonglong2*)(wp + 2 * DD * 16);
#pragma unroll
        for (int g = 0; g < TGH; ++g) {
            ulonglong2 ov = *(const ulonglong2*)(op + g * (DD * 4));
            a0[g] = fma2(wr.x, ov.x, a0[g]);
            a0[g] = fma2(wr.y, ov.y, a0[g]);
            a1[g] = fma2(wz.x, ov.x, a1[g]);
            a1[g] = fma2(wz.y, ov.y, a1[g]);
            a2[g] = fma2(wn.x, ov.x, a2[g]);
            a2[g] = fma2(wn.y, ov.y, a2[g]);
        }
        wp += GD * 16;
        op += 16;
    }

    if (side) {
        // hh: publish partials for groups [gb, gb+TGH)
#pragma unroll
        for (int g = 0; g < TGH; ++g) {
            float* p = ph + (gb + g) * (3 * DD);
            p[d]          = red2(a0[g]);
            p[DD + d]     = red2(a1[g]);
            p[2 * DD + d] = red2(a2[g]);
        }
        __syncthreads();   // partials visible
        __syncthreads();   // wait for ih h-update
    } else {
        __syncthreads();   // wait for hh partials
#pragma unroll
        for (int g = 0; g < TGH; ++g) {
            const float* p = ph + (gb + g) * (3 * DD);
            float hr = p[d];
            float hz = p[DD + d];
            float hn = p[2 * DD + d];
            float r  = sigmoidf_(red2(a0[g]) + hr);
            float z  = sigmoidf_(red2(a1[g]) + hz);
            float n  = tanhf_(fmaf(r, hn, red2(a2[g])));
            float h  = hstate[(gb + g) * DD + d];
            float hnew = fmaf(z, h - n, n);            // (1-z)n + z h
            hstate[(gb + g) * DD + d] = hnew;
            if (accs) accs[(gb + g) * DD + d] += hnew;
        }
        __syncthreads();   // new h visible to hh side
    }
}

// ---------------- main persistent kernel ----------------
__global__ __launch_bounds__(NT, 1) void gru_main(
    const float* __restrict__ x,
    const float* __restrict__ bih0, const float* __restrict__ bhh0,
    const float* __restrict__ bih1, const float* __restrict__ bhh1,
    float* __restrict__ out, int B)
{
    extern __shared__ float sm[];
    float* xs   = sm;                     // [TG][DD]
    float* h0s  = sm + 1 * TG * DD;       // [TG][DD]
    float* h1s  = sm + 2 * TG * DD;       // [TG][DD]
    float* accs = sm + 3 * TG * DD;       // [TG][DD]
    float* ph   = sm + 4 * TG * DD;       // [TG][3][DD]
    int*   ord  = (int*)(sm + 7 * TG * DD); // [TG][LL]

    const int tid  = threadIdx.x;
    const int wg   = tid >> 8;
    const int side = wg >> 1;             // 0 = ih, 1 = hh
    const int gb   = (wg & 1) * TGH;      // group-half base
    const int d    = tid & (DD - 1);
    const int g0   = blockIdx.x * TG;

    // stage group order into smem (once)
    for (int k = tid; k < TG * LL; k += NT) {
        const int g   = k / LL;
        const int grp = g0 + g;
        ord[k] = (grp < B) ? g_order[grp * LL + (k - g * LL)] : -1;
    }
    // zero h0s, h1s, accs (contiguous)
    for (int i = tid; i < 3 * TG * DD; i += NT) h0s[i] = 0.f;
    __syncthreads();

    const float* bv0 = side ? bhh0 : bih0;
    const float* bv1 = side ? bhh1 : bih1;
    const float4* w0 = g_wpack + (size_t)(side ? 1 : 0) * 64 * GD;
    const float4* w1 = g_wpack + (size_t)(side ? 3 : 2) * 64 * GD;

#pragma unroll 1
    for (int t = 0; t < LL; ++t) {
        // gather x_t for all groups (zeros for pads)
        for (int k = tid; k < TG * DD; k += NT) {
            const int g  = k >> 8;
            const int dd = k & (DD - 1);
            const int e  = ord[g * LL + t];
            xs[k] = (e >= 0) ? x[(size_t)e * DD + dd] : 0.f;
        }
        __syncthreads();

        // layer 0: ih streams xs, hh streams h0s; ih updates h0s
        layer_pass(w0, bv0, side ? h0s : xs, h0s, ph, nullptr, side, gb, d);
        // layer 1: ih streams new h0s, hh streams h1s; ih updates h1s + pool
        layer_pass(w1, bv1, side ? h1s : h0s, h1s, ph, accs, side, gb, d);
    }

    if (side == 0) {
#pragma unroll
        for (int g = 0; g < TGH; ++g) {
            const int grp = g0 + gb + g;
            if (grp < B) out[(size_t)grp * DD + d] = accs[(gb + g) * DD + d] * (1.0f / LL);
        }
    }
}

// ---------------- entry point ----------------
extern "C" void kernel_launch(void* const* d_in, const int* in_sizes, int n_in,
                              void* d_out, int out_size) {
    const float* x     = (const float*)d_in[0];
    const float* ts    = (const float*)d_in[1];
    const float* wih0  = (const float*)d_in[2];
    const float* whh0  = (const float*)d_in[3];
    const float* bih0  = (const float*)d_in[4];
    const float* bhh0  = (const float*)d_in[5];
    const float* wih1  = (const float*)d_in[6];
    const float* whh1  = (const float*)d_in[7];
    const float* bih1  = (const float*)d_in[8];
    const float* bhh1  = (const float*)d_in[9];
    const int*   index = (const int*)d_in[10];
    float* out = (float*)d_out;

    const int E = in_sizes[0] / DD;
    const int B = out_size / DD;

    const int smem = (7 * TG * DD) * (int)sizeof(float) + (TG * LL) * (int)sizeof(int);
    cudaFuncSetAttribute(gru_main, cudaFuncAttributeMaxDynamicSharedMemorySize, smem);

    setup_k<<<B + 768, 256>>>(ts, index, E, B, wih0, whh0, wih1, whh1);

    const int nb = (B + TG - 1) / TG;   // 147 blocks for B=2048 -> one wave on 148 SMs
    gru_main<<<nb, NT, smem>>>(x, bih0, bhh0, bih1, bhh1, out, B);
}